// round 4
// baseline (speedup 1.0000x reference)
#include <cuda_runtime.h>
#include <cstdint>

// IDWT_2D: x [B=4, 4*C=256, H=256, W=256] f32, filters [4,2,2] f32
// s[b,g,h,w] = sum_n x[b, n*64+g, h, w]
// y[b, g*4+j, 2h+a, 2w+c] = s[b,g,h,w] * f[j,a,c]
// Output: [4, 256, 512, 512] f32

static constexpr int B = 4;
static constexpr int C = 64;                 // groups
static constexpr int H = 256;
static constexpr int W = 256;
static constexpr int SUBBAND_STRIDE = C * H * W;      // offset between sub-bands n
static constexpr int OUT_W = 2 * W;                   // 512
static constexpr int OUT_CH_STRIDE = (2 * H) * OUT_W; // 512*512

// One warp = one full (b, g, h) input row (256 pixels).
// Thread k owns pixel pairs {64m + 2k, 64m + 2k + 1} for m = 0..3.
// Loads: 16 coalesced LDG.64 per thread-warp (high MLP).
// Stores: 32 STG.128, each one a lane-contiguous 512B full-sector block.
__global__ __launch_bounds__(256) void idwt2d_kernel(
    const float* __restrict__ x,
    const float* __restrict__ filters,
    float* __restrict__ out)
{
    unsigned seg = blockIdx.x * 8u + (threadIdx.x >> 5);  // global warp id
    int lane = threadIdx.x & 31;
    int h = seg & (H - 1);
    int g = (seg >> 8) & (C - 1);
    int b = seg >> 14;

    // input row base for sub-band 0, this lane
    const float* xb = x + (((size_t)(b * 4 * C + g) * H + h) * W) + 2 * lane;

    // gather + sum the 4 sub-bands; 4 pixel-pairs per thread (m = 0..3)
    float2 s[4];
    #pragma unroll
    for (int m = 0; m < 4; ++m)
        s[m] = *reinterpret_cast<const float2*>(xb + 64 * m);
    #pragma unroll
    for (int n = 1; n < 4; ++n) {
        #pragma unroll
        for (int m = 0; m < 4; ++m) {
            float2 t = *reinterpret_cast<const float2*>(
                xb + n * SUBBAND_STRIDE + 64 * m);
            s[m].x += t.x; s[m].y += t.y;
        }
    }

    // filters: [4,2,2] -> one float4 per j: {a0c0, a0c1, a1c0, a1c1}
    const float4* f4 = reinterpret_cast<const float4*>(filters);

    // output base: channel g*4, row 2h, column 4*lane
    float* obase = out + ((size_t)(b * 4 * C + g * 4) * (2 * H) + 2 * h) * OUT_W
                       + 4 * lane;

    #pragma unroll
    for (int j = 0; j < 4; ++j) {
        float4 F = __ldg(f4 + j);
        float* orow = obase + (size_t)j * OUT_CH_STRIDE;

        #pragma unroll
        for (int m = 0; m < 4; ++m) {
            float4 v;
            // a = 0 row, 512B block m
            v.x = s[m].x * F.x; v.y = s[m].x * F.y;
            v.z = s[m].y * F.x; v.w = s[m].y * F.y;
            reinterpret_cast<float4*>(orow + 128 * m)[0] = v;
            // a = 1 row, 512B block m
            v.x = s[m].x * F.z; v.y = s[m].x * F.w;
            v.z = s[m].y * F.z; v.w = s[m].y * F.w;
            reinterpret_cast<float4*>(orow + OUT_W + 128 * m)[0] = v;
        }
    }
}

extern "C" void kernel_launch(void* const* d_in, const int* in_sizes, int n_in,
                              void* d_out, int out_size) {
    const float* x       = (const float*)d_in[0];
    const float* filters = (const float*)d_in[1];
    float* out           = (float*)d_out;

    // total warps = B*C*H = 65536 ; 8 warps/block -> 8192 blocks
    idwt2d_kernel<<<8192, 256>>>(x, filters, out);
}

// round 5
// speedup vs baseline: 1.0157x; 1.0157x over previous
#include <cuda_runtime.h>
#include <cstdint>

// IDWT_2D: x [B=4, 4*C=256, H=256, W=256] f32, filters [4,2,2] f32
// s[b,g,h,w] = sum_n x[b, n*64+g, h, w]
// y[b, g*4+j, 2h+a, 2w+c] = s[b,g,h,w] * f[j,a,c]
// Output: [4, 256, 512, 512] f32

static constexpr int B = 4;
static constexpr int C = 64;                 // groups
static constexpr int H = 256;
static constexpr int W = 256;
static constexpr int SUBBAND_STRIDE = C * H * W;      // offset between sub-bands n
static constexpr int OUT_W = 2 * W;                   // 512
static constexpr int OUT_CH_STRIDE = (2 * H) * OUT_W; // 512*512

// One warp handles one (b, g, h, half) = 128 consecutive input pixels.
// Thread k holds input pixels {2k, 2k+1} (s0) and {64+2k, 64+2k+1} (s1).
// Every STG.128 across the warp is a contiguous 512B full-sector block.
// __launch_bounds__(256, 8): cap regs at 32 -> 8 blocks/SM -> 64 warps (100% occ).
__global__ __launch_bounds__(256, 8) void idwt2d_kernel(
    const float* __restrict__ x,
    const float* __restrict__ filters,
    float* __restrict__ out)
{
    unsigned seg = blockIdx.x * 8u + (threadIdx.x >> 5);  // global warp id
    int lane = threadIdx.x & 31;
    int half = seg & 1;                 // which half of the input row
    int h    = (seg >> 1) & (H - 1);
    int g    = (seg >> 9) & (C - 1);
    int b    = seg >> 15;

    // input row base for sub-band 0, this warp's half-row, this lane
    const float* xb = x + (((size_t)(b * 4 * C + g) * H + h) * W)
                        + half * 128 + 2 * lane;

    // gather + sum the 4 sub-bands (coalesced float2 loads: 8B/lane)
    float2 s0 = *reinterpret_cast<const float2*>(xb);
    float2 s1 = *reinterpret_cast<const float2*>(xb + 64);
    #pragma unroll
    for (int n = 1; n < 4; ++n) {
        float2 t0 = *reinterpret_cast<const float2*>(xb + n * SUBBAND_STRIDE);
        float2 t1 = *reinterpret_cast<const float2*>(xb + n * SUBBAND_STRIDE + 64);
        s0.x += t0.x; s0.y += t0.y;
        s1.x += t1.x; s1.y += t1.y;
    }

    // filters: [4,2,2] -> one float4 per j: {a0c0, a0c1, a1c0, a1c1}
    const float4* f4 = reinterpret_cast<const float4*>(filters);

    // output base: channel g*4, row 2h, column 256*half + 4*lane
    float* obase = out + ((size_t)(b * 4 * C + g * 4) * (2 * H) + 2 * h) * OUT_W
                       + half * 256 + 4 * lane;

    #pragma unroll
    for (int j = 0; j < 4; ++j) {
        float4 F = __ldg(f4 + j);
        float* orow = obase + (size_t)j * OUT_CH_STRIDE;

        float4 v;
        // a = 0, first 512B block (from s0: pixels 2k, 2k+1)
        v.x = s0.x * F.x; v.y = s0.x * F.y; v.z = s0.y * F.x; v.w = s0.y * F.y;
        reinterpret_cast<float4*>(orow)[0] = v;
        // a = 0, second 512B block (from s1: pixels 64+2k, 64+2k+1)
        v.x = s1.x * F.x; v.y = s1.x * F.y; v.z = s1.y * F.x; v.w = s1.y * F.y;
        reinterpret_cast<float4*>(orow + 128)[0] = v;
        // a = 1 row
        v.x = s0.x * F.z; v.y = s0.x * F.w; v.z = s0.y * F.z; v.w = s0.y * F.w;
        reinterpret_cast<float4*>(orow + OUT_W)[0] = v;
        v.x = s1.x * F.z; v.y = s1.x * F.w; v.z = s1.y * F.z; v.w = s1.y * F.w;
        reinterpret_cast<float4*>(orow + OUT_W + 128)[0] = v;
    }
}

extern "C" void kernel_launch(void* const* d_in, const int* in_sizes, int n_in,
                              void* d_out, int out_size) {
    const float* x       = (const float*)d_in[0];
    const float* filters = (const float*)d_in[1];
    float* out           = (float*)d_out;

    // total warps = B*C*H*2 = 131072 ; 8 warps/block -> 16384 blocks
    idwt2d_kernel<<<16384, 256>>>(x, filters, out);
}